// round 10
// baseline (speedup 1.0000x reference)
#include <cuda_runtime.h>
#include <cstdint>

// Problem constants
#define BB 8
#define NN 256
#define FF 64      // OUT_F == OUT_E
#define KE 32      // IN_E
#define KN 64      // IN_F
#define NODE_OUT_ELEMS (BB * NN * FF)
#define NTILES (2 * BB * NN)     // 4096 half-tiles (128 rows each)
#define GRID_EDGE 444            // 3 CTAs/SM x 148 SMs, persistent

typedef unsigned long long u64;

// ---------------- packed f32x2 helpers ----------------
__device__ __forceinline__ u64 ffma2(u64 a, u64 b, u64 c) {
    u64 d; asm("fma.rn.f32x2 %0, %1, %2, %3;" : "=l"(d) : "l"(a), "l"(b), "l"(c)); return d;
}
__device__ __forceinline__ u64 fmul2(u64 a, u64 b) {
    u64 d; asm("mul.rn.f32x2 %0, %1, %2;" : "=l"(d) : "l"(a), "l"(b)); return d;
}
__device__ __forceinline__ u64 fadd2(u64 a, u64 b) {
    u64 d; asm("add.rn.f32x2 %0, %1, %2;" : "=l"(d) : "l"(a), "l"(b)); return d;
}
__device__ __forceinline__ u64 pack2(float lo, float hi) {
    u64 r; asm("mov.b64 %0, {%1, %2};" : "=l"(r) : "f"(lo), "f"(hi)); return r;
}
__device__ __forceinline__ float2 unpack2(u64 v) {
    float2 r; asm("mov.b64 {%0, %1}, %2;" : "=f"(r.x), "=f"(r.y) : "l"(v)); return r;
}
__device__ __forceinline__ uint32_t tf32_rna(float v) {
    uint32_t h; asm("cvt.rna.tf32.f32 %0, %1;" : "=r"(h) : "f"(v));
    return h;
}

// ---------------- cp.async helpers ----------------
__device__ __forceinline__ uint32_t smem_u32(const void* p) {
    uint32_t a;
    asm("{ .reg .u64 t; cvta.to.shared.u64 t, %1; cvt.u32.u64 %0, t; }" : "=r"(a) : "l"(p));
    return a;
}
__device__ __forceinline__ void cpa16(uint32_t saddr, const void* g) {
    asm volatile("cp.async.cg.shared.global [%0], [%1], 16;" :: "r"(saddr), "l"(g));
}
__device__ __forceinline__ void cpa_commit() {
    asm volatile("cp.async.commit_group;");
}
__device__ __forceinline__ void cpa_wait1() {
    asm volatile("cp.async.wait_group 1;");
}
__device__ __forceinline__ void stg_cs_f2(float* p, float x, float y) {
    asm volatile("st.global.cs.v2.f32 [%0], {%1, %2};" :: "l"(p), "f"(x), "f"(y));
}

// ---------------- tf32 mma.sync (layout verified R5/R7/R8) ----------------
__device__ __forceinline__ void mma_tf32(float* c, const uint32_t* a, const uint32_t* b) {
    asm volatile(
        "mma.sync.aligned.m16n8k8.row.col.f32.tf32.tf32.f32 "
        "{%0,%1,%2,%3}, {%4,%5,%6,%7}, {%8,%9}, {%0,%1,%2,%3};"
        : "+f"(c[0]), "+f"(c[1]), "+f"(c[2]), "+f"(c[3])
        : "r"(a[0]), "r"(a[1]), "r"(a[2]), "r"(a[3]), "r"(b[0]), "r"(b[1]));
}

// ---------------- scratch ----------------
__device__ float g_rsx[BB * NN * FF];        // relu(node_sx)
// node_x pre-scattered into epilogue fragment layout:
// float2 index: ((((b*2+half)*8 + w)*2 + rs)*8 + nt)*32 + lane
// row m = half*128 + w*16 + rs*8 + (lane>>2); pair f = nt*8 + 2*(lane&3) + {0,1}
__device__ float  g_nxF[BB * NN * FF];       // 512 KB
__device__ float2 g_part[2 * BB * NN * 32];  // per-half partial agg sums
// interleaved B fragment packs: uint4 {bh0, bh1, bl0, bl1} at [(nt*4+ks)*32 + lane]
__device__ uint4 g_Bp[8 * 4 * 32];           // 16 KB

// ============================================================
// Kernel 1: node projections (+ CTA 0: B pack prep)
// ============================================================
__global__ void __launch_bounds__(256) node_proj_kernel(
    const float* __restrict__ emb_node,
    const float* __restrict__ W_node, const float* __restrict__ b_node,
    const float* __restrict__ W_nodes, const float* __restrict__ b_nodes,
    const float* __restrict__ W_edge)
{
    __shared__ float wsm0[KN * FF];
    __shared__ float wsm1[KN * FF];
    __shared__ float rsm[8 * KN];

    const int tid = threadIdx.x;
    const int row0 = blockIdx.x * 8;

    if (blockIdx.x == 0) {
        // B fragment packs (interleaved hi/lo)
        #pragma unroll
        for (int i = 0; i < 4; i++) {
            int idx = tid + i * 256;              // 0..1023
            int lane = idx & 31;
            int ks   = (idx >> 5) & 3;
            int nt   = idx >> 7;
            int k0 = ks * 8 + (lane & 3);
            int f  = nt * 8 + (lane >> 2);
            float v0 = W_edge[k0 * FF + f];
            float v1 = W_edge[(k0 + 4) * FF + f];
            uint32_t h0 = tf32_rna(v0), h1 = tf32_rna(v1);
            uint4 p;
            p.x = h0; p.y = h1;
            p.z = tf32_rna(v0 - __uint_as_float(h0));
            p.w = tf32_rna(v1 - __uint_as_float(h1));
            g_Bp[idx] = p;
        }
    }

    {
        const float4* w0 = (const float4*)W_node;
        const float4* w1 = (const float4*)W_nodes;
        #pragma unroll
        for (int i = tid; i < KN * FF / 4; i += 256) {
            ((float4*)wsm0)[i] = w0[i];
            ((float4*)wsm1)[i] = w1[i];
        }
        if (tid < 128)
            ((float4*)rsm)[tid] = ((const float4*)(emb_node + (size_t)row0 * KN))[tid];
    }
    __syncthreads();

    const int rl = tid >> 6;
    const int f  = tid & 63;

    float nx0 = b_node[f], sx0 = b_nodes[f];
    float nx1 = nx0,       sx1 = sx0;
    #pragma unroll
    for (int k = 0; k < KN; k++) {
        float a0 = rsm[rl * KN + k];
        float a1 = rsm[(rl + 4) * KN + k];
        float w0 = wsm0[k * FF + f];
        float w1 = wsm1[k * FF + f];
        nx0 = fmaf(a0, w0, nx0);  sx0 = fmaf(a0, w1, sx0);
        nx1 = fmaf(a1, w0, nx1);  sx1 = fmaf(a1, w1, sx1);
    }

    // scatter node_x into fragment layout (half/warp/rs indexing)
    const int nt = f >> 3;
    const int cc = (f >> 1) & 3;
    const int j  = f & 1;
    {
        const int ga = row0 + rl;
        const int bbv = ga >> 8, m = ga & 255;
        const int hf = m >> 7, wi = (m >> 4) & 7, rs = (m >> 3) & 1;
        const int lp = ((m & 7) << 2) | cc;
        g_nxF[(size_t)((((((bbv * 2 + hf) * 8 + wi) * 2 + rs) * 8 + nt) * 32 + lp) * 2 + j)] = nx0;
        g_rsx[(size_t)ga * FF + f] = fmaxf(sx0, 0.0f);
    }
    {
        const int gb = row0 + rl + 4;
        const int bbv = gb >> 8, m = gb & 255;
        const int hf = m >> 7, wi = (m >> 4) & 7, rs = (m >> 3) & 1;
        const int lp = ((m & 7) << 2) | cc;
        g_nxF[(size_t)((((((bbv * 2 + hf) * 8 + wi) * 2 + rs) * 8 + nt) * 32 + lp) * 2 + j)] = nx1;
        g_rsx[(size_t)gb * FF + f] = fmaxf(sx1, 0.0f);
    }
}

// ============================================================
// Kernel 2: PERSISTENT — 444 CTAs loop over 4096 half-tiles.
//   B-pack staged once; A double-buffered via cp.async groups.
//   Per tile: 128 m x 64 f x 32 k, tf32 mma.sync (3xTF32);
//   8 warps; warp w owns m-tile w (rows 16w..16w+16), all 8 n-tiles.
// ============================================================
#define OFF_BES  0          // 256 B bias
#define OFF_RED  256        // 2048 B (8 warps x 32 float2)
#define OFF_B    2304       // 16384 B interleaved B frag packs
#define OFF_STG  18688      // 2 stages
#define STG_RAW  0          // 18432 B raw A (rows padded to 36 floats)
#define STG_AROW 18432      // 512 B A slice
#define STG_SZ   18944
#define EDGE_SMEM_TOTAL (OFF_STG + 2 * STG_SZ)   // 56576

__device__ __forceinline__ void prefetch_tile(
    uint32_t sb, int stg, int t, int tid,
    const float* __restrict__ emb_edge, const float* __restrict__ A)
{
    const int g = t >> 1, half = t & 1;
    const uint32_t base = sb + OFF_STG + stg * STG_SZ;
    const float4* esrc = (const float4*)(emb_edge + ((size_t)g * NN + half * 128) * KE);
    #pragma unroll
    for (int i = 0; i < 4; i++) {
        int c = tid + i * 256;            // 0..1023 16B chunks (128 rows x 8)
        int row = c >> 3, c8 = c & 7;
        cpa16(base + STG_RAW + row * 144 + c8 * 16, esrc + c);
    }
    if (tid < 32)
        cpa16(base + STG_AROW + tid * 16,
              ((const float4*)(A + (size_t)g * NN + half * 128)) + tid);
}

__global__ void __launch_bounds__(256, 3) edge_kernel(
    const float* __restrict__ A,
    const float* __restrict__ emb_edge,
    const float* __restrict__ b_edge,
    float* __restrict__ out)
{
    extern __shared__ char smem[];
    const uint32_t sb = smem_u32(smem);
    const int tid  = threadIdx.x;
    const int w    = tid >> 5;
    const int lane = tid & 31;

    // ---- prologue: B-pack + bias + first tile, one group ----
    {
        #pragma unroll
        for (int i = 0; i < 4; i++) {
            int c = tid + i * 256;            // 1024 chunks of B pack
            cpa16(sb + OFF_B + c * 16, ((const uint4*)g_Bp) + c);
        }
        if (tid < 16)
            cpa16(sb + OFF_BES + tid * 16, ((const float4*)b_edge) + tid);
        prefetch_tile(sb, 0, blockIdx.x, tid, emb_edge, A);
        cpa_commit();
    }

    const uint4* Bsm = (const uint4*)(smem + OFF_B);
    int stg = 0;

    for (int t = blockIdx.x; t < NTILES; t += GRID_EDGE, stg ^= 1) {
        // prefetch next tile into alternate buffer (overlaps this tile's compute)
        const int tn = t + GRID_EDGE;
        if (tn < NTILES) prefetch_tile(sb, stg ^ 1, tn, tid, emb_edge, A);
        cpa_commit();
        cpa_wait1();             // current tile's group (and older) complete
        __syncthreads();

        const int g    = t >> 1;
        const int half = t & 1;
        const int b    = g >> 8;
        const char* buf = smem + OFF_STG + stg * STG_SZ;
        const float* raw  = (const float*)(buf + STG_RAW);
        const float* Asmf = (const float*)(buf + STG_AROW);
        const float* bes  = (const float*)(smem + OFF_BES);

        // ---- GEMM: 1 m-tile x 8 n-tiles x 4 k-steps x 3 passes ----
        float acc[8][4];
        #pragma unroll
        for (int nt = 0; nt < 8; nt++)
            #pragma unroll
            for (int j = 0; j < 4; j++) acc[nt][j] = 0.0f;

        #pragma unroll
        for (int ks = 0; ks < 4; ks++) {
            uint32_t ah[4], al[4];
            {
                const int r0 = w * 16 + (lane >> 2);
                const int c0 = ks * 8 + (lane & 3);
                float v0 = raw[r0 * 36 + c0];
                float v1 = raw[(r0 + 8) * 36 + c0];
                float v2 = raw[r0 * 36 + c0 + 4];
                float v3 = raw[(r0 + 8) * 36 + c0 + 4];
                ah[0] = tf32_rna(v0); ah[1] = tf32_rna(v1);
                ah[2] = tf32_rna(v2); ah[3] = tf32_rna(v3);
                al[0] = tf32_rna(v0 - __uint_as_float(ah[0]));
                al[1] = tf32_rna(v1 - __uint_as_float(ah[1]));
                al[2] = tf32_rna(v2 - __uint_as_float(ah[2]));
                al[3] = tf32_rna(v3 - __uint_as_float(ah[3]));
            }
            #pragma unroll
            for (int nt = 0; nt < 8; nt++) {
                uint4 Bv = Bsm[(nt * 4 + ks) * 32 + lane];
                uint32_t bh[2] = {Bv.x, Bv.y};
                uint32_t bl[2] = {Bv.z, Bv.w};
                mma_tf32(acc[nt], ah, bh);
                mma_tf32(acc[nt], al, bh);
                mma_tf32(acc[nt], ah, bl);
            }
        }

        // ---- epilogue ----
        float* eout = out + NODE_OUT_ELEMS + (size_t)g * (NN * FF);
        const float2* nxw =
            ((const float2*)g_nxF) + ((size_t)((b * 2 + half) * 8 + w)) * 512;

        u64 part[8];
        #pragma unroll
        for (int nt = 0; nt < 8; nt++) part[nt] = 0ull;

        #pragma unroll
        for (int rs = 0; rs < 2; rs++) {
            const int ml = w * 16 + rs * 8 + (lane >> 2);   // local row
            const int m  = half * 128 + ml;                 // global row
            const float Am = Asmf[ml];
            const u64 A2 = pack2(Am, Am);
            #pragma unroll
            for (int nt = 0; nt < 8; nt++) {
                const int fo = nt * 8 + 2 * (lane & 3);
                float ex = acc[nt][rs * 2 + 0] + bes[fo];
                float ey = acc[nt][rs * 2 + 1] + bes[fo + 1];
                stg_cs_f2(&eout[(size_t)m * FF + fo], fmaxf(ex, 0.f), fmaxf(ey, 0.f));
                float2 nx = __ldg(&nxw[(rs * 8 + nt) * 32 + lane]);
                part[nt] = ffma2(fmul2(A2, pack2(nx.x, nx.y)), pack2(ex, ey), part[nt]);
            }
        }

        // reduce over the 8 row-slots in the warp (bits of lane>>2)
        #pragma unroll
        for (int d = 4; d <= 16; d <<= 1) {
            #pragma unroll
            for (int nt = 0; nt < 8; nt++)
                part[nt] = fadd2(part[nt], __shfl_xor_sync(0xffffffffu, part[nt], d));
        }
        if (lane < 4) {
            float2* red = (float2*)(smem + OFF_RED);
            #pragma unroll
            for (int nt = 0; nt < 8; nt++)
                red[w * 32 + nt * 4 + lane] = unpack2(part[nt]);
        }
        __syncthreads();   // also orders raw-buffer reads before next prefetch reuse

        if (tid < 32) {
            const float2* red = (const float2*)(smem + OFF_RED);
            float2 s = red[tid];
            #pragma unroll
            for (int q = 1; q < 8; q++) {
                float2 v = red[q * 32 + tid];
                s.x += v.x; s.y += v.y;
            }
            g_part[(size_t)t * 32 + tid] = s;
        }
    }
}

// ============================================================
// Kernel 3: combine halves -> node_out = relu(p0+p1) + rsx
// ============================================================
__global__ void __launch_bounds__(256) finish_kernel(float* __restrict__ out)
{
    const int idx = blockIdx.x * 256 + threadIdx.x;   // 0..65535
    const int g  = idx >> 5;
    const int fp = idx & 31;
    float2 a = g_part[(size_t)(2 * g) * 32 + fp];
    float2 b = g_part[(size_t)(2 * g + 1) * 32 + fp];
    float2 r = *(const float2*)&g_rsx[(size_t)g * FF + 2 * fp];
    float2 o;
    o.x = fmaxf(a.x + b.x, 0.0f) + r.x;
    o.y = fmaxf(a.y + b.y, 0.0f) + r.y;
    *(float2*)&out[(size_t)g * FF + 2 * fp] = o;
}

// ============================================================
// launch
// ============================================================
extern "C" void kernel_launch(void* const* d_in, const int* in_sizes, int n_in,
                              void* d_out, int out_size)
{
    const float* A        = (const float*)d_in[0];
    const float* emb_node = (const float*)d_in[1];
    const float* emb_edge = (const float*)d_in[2];
    const float* W_node   = (const float*)d_in[3];
    const float* b_node   = (const float*)d_in[4];
    const float* W_nodes  = (const float*)d_in[5];
    const float* b_nodes  = (const float*)d_in[6];
    const float* W_edge   = (const float*)d_in[7];
    const float* b_edge   = (const float*)d_in[8];
    float* out = (float*)d_out;

    static int attr_set = 0;
    if (!attr_set) {
        cudaFuncSetAttribute(edge_kernel,
                             cudaFuncAttributeMaxDynamicSharedMemorySize, EDGE_SMEM_TOTAL);
        attr_set = 1;
    }

    node_proj_kernel<<<256, 256>>>(emb_node, W_node, b_node, W_nodes, b_nodes, W_edge);
    edge_kernel<<<GRID_EDGE, 256, EDGE_SMEM_TOTAL>>>(A, emb_edge, b_edge, out);
    finish_kernel<<<256, 256>>>(out);
}